// round 2
// baseline (speedup 1.0000x reference)
#include <cuda_runtime.h>

#define BS   4
#define NN   2048
#define CIN  128
#define COUT 64
#define H    4
#define HD   256   // H*COUT

#define TI 128
#define TJ 128
#define TIP (TI + 1)   // pad for conflict-free transposed P

// Scratch (device globals: allocation-free)
__device__ float g_hs[BS * H * NN * COUT];   // [b][h][n][d] head-major
__device__ float g_el[BS * H * NN];
__device__ float g_er[BS * H * NN];
__device__ float g_emax[BS * H];

// ---------------- packed f32x2 helpers ----------------
__device__ __forceinline__ unsigned long long pack2(float x) {
    unsigned long long r;
    asm("mov.b64 %0, {%1, %1};" : "=l"(r) : "f"(x));
    return r;
}
__device__ __forceinline__ void ffma2(unsigned long long &c, unsigned long long a,
                                      unsigned long long b) {
    asm("fma.rn.f32x2 %0, %1, %2, %0;" : "+l"(c) : "l"(a), "l"(b));
}
__device__ __forceinline__ float2 unpack2(unsigned long long v) {
    float2 f;
    asm("mov.b64 {%0, %1}, %2;" : "=f"(f.x), "=f"(f.y) : "l"(v));
    return f;
}

// ---------------- K1: hs = xs @ W1 (per-head 64x64 tiles) + el/er ----------------
__global__ __launch_bounds__(256) void k1_gemm(const float* __restrict__ xs,
                                               const float* __restrict__ W1,
                                               const float* __restrict__ a_l,
                                               const float* __restrict__ a_r) {
    const int bx   = blockIdx.x;   // row tile (64 rows)
    const int head = blockIdx.y;
    const int b    = blockIdx.z;
    const int tid  = threadIdx.x;
    const int ig = tid >> 4, cg = tid & 15;
    const int r0 = ig * 4, c0 = cg * 4;

    __shared__ float As[32][68];
    __shared__ float Bs[32][68];
    __shared__ float sred[16][64];

    float acc[4][4] = {};
    const float* xbase = xs + ((size_t)(b * NN + bx * 64)) * CIN;
    const float* wbase = W1 + head * COUT;

    for (int kc = 0; kc < CIN; kc += 32) {
        // A tile (transposed): 64 rows x 32 k
        int lin = tid;
        #pragma unroll
        for (int t = 0; t < 2; t++, lin += 256) {
            int r = lin >> 3, k4 = lin & 7;
            float4 v = *(const float4*)(xbase + r * CIN + kc + k4 * 4);
            As[k4 * 4 + 0][r] = v.x; As[k4 * 4 + 1][r] = v.y;
            As[k4 * 4 + 2][r] = v.z; As[k4 * 4 + 3][r] = v.w;
        }
        // B tile: 32 k x 64 cols
        lin = tid;
        #pragma unroll
        for (int t = 0; t < 2; t++, lin += 256) {
            int k = lin >> 4, c4 = lin & 15;
            float4 v = *(const float4*)(wbase + (size_t)(kc + k) * HD + c4 * 4);
            *(float4*)&Bs[k][c4 * 4] = v;
        }
        __syncthreads();
        #pragma unroll
        for (int k = 0; k < 32; k++) {
            float4 aq = *(const float4*)&As[k][r0];
            float4 bq = *(const float4*)&Bs[k][c0];
            float ar[4] = {aq.x, aq.y, aq.z, aq.w};
            float br[4] = {bq.x, bq.y, bq.z, bq.w};
            #pragma unroll
            for (int r = 0; r < 4; r++)
                #pragma unroll
                for (int c = 0; c < 4; c++)
                    acc[r][c] += ar[r] * br[c];
        }
        __syncthreads();
    }

    // write hs + reduce el/er
    const int bh = b * H + head;
    float* hsbase = g_hs + ((size_t)(bh * NN + bx * 64)) * COUT;
    float pl[4] = {}, pr[4] = {};
    #pragma unroll
    for (int r = 0; r < 4; r++) {
        float4 w = {acc[r][0], acc[r][1], acc[r][2], acc[r][3]};
        *(float4*)(hsbase + (size_t)(r0 + r) * COUT + c0) = w;
        #pragma unroll
        for (int c = 0; c < 4; c++) {
            float al = __ldg(a_l + c0 + c), ar_ = __ldg(a_r + c0 + c);
            pl[r] += acc[r][c] * al;
            pr[r] += acc[r][c] * ar_;
        }
    }
    #pragma unroll
    for (int r = 0; r < 4; r++) sred[cg][r0 + r] = pl[r];
    __syncthreads();
    if (tid < 64) {
        float s = 0.f;
        #pragma unroll
        for (int g = 0; g < 16; g++) s += sred[g][tid];
        g_el[(size_t)bh * NN + bx * 64 + tid] = s;
    }
    __syncthreads();
    #pragma unroll
    for (int r = 0; r < 4; r++) sred[cg][r0 + r] = pr[r];
    __syncthreads();
    if (tid < 64) {
        float s = 0.f;
        #pragma unroll
        for (int g = 0; g < 16; g++) s += sred[g][tid];
        g_er[(size_t)bh * NN + bx * 64 + tid] = s;
    }
}

// ---------------- K1b: E = max_j er ----------------
__global__ void k1b_max() {
    const int bh = blockIdx.x;
    __shared__ float sm[256];
    float m = -1e30f;
    for (int i = threadIdx.x; i < NN; i += 256)
        m = fmaxf(m, g_er[(size_t)bh * NN + i]);
    sm[threadIdx.x] = m;
    __syncthreads();
    for (int s = 128; s > 0; s >>= 1) {
        if (threadIdx.x < s) sm[threadIdx.x] = fmaxf(sm[threadIdx.x], sm[threadIdx.x + s]);
        __syncthreads();
    }
    if (threadIdx.x == 0) g_emax[bh] = sm[0];
}

// ---------------- K2: fused masked-softmax attention + P@V ----------------
__global__ __launch_bounds__(256, 2) void k2_attn(const float* __restrict__ adjs,
                                                  float* __restrict__ out) {
    const int it0  = blockIdx.x * TI;
    const int head = blockIdx.y;
    const int b    = blockIdx.z;
    const int bh   = b * H + head;
    const int tid  = threadIdx.x;

    extern __shared__ float smem[];
    float* sP   = smem;                 // [TJ][TIP] transposed P
    float* sHS  = sP + TJ * TIP;        // [TJ][COUT]
    float* sel  = sHS + TJ * COUT;      // [TI]
    float* selm = sel + TI;             // [TI] row shift m_i
    float* ser  = selm + TI;            // [TJ]
    float* sl   = ser + TJ;             // [TI] 1/l
    float* sred = sl + TI;              // [256]

    const int ig = tid >> 3, dg = tid & 7;
    const int i0 = ig * 4, d0 = dg * 8;

    // per-row shift m_i = leaky(el_i + E)  (upper bound over all j)
    {
        float E = g_emax[bh];
        if (tid < TI) {
            float e = g_el[(size_t)bh * NN + it0 + tid];
            sel[tid] = e;
            float s = e + E;
            selm[tid] = fmaxf(s, 0.1f * s);
        }
    }

    unsigned long long acc[4][4];
    #pragma unroll
    for (int r = 0; r < 4; r++)
        #pragma unroll
        for (int c = 0; c < 4; c++) acc[r][c] = 0ull;
    float lacc = 0.f;

    const float* abase = adjs + ((size_t)(b * NN + it0)) * NN;
    const int li = tid & 127;        // row for l-pass
    const int ljb = (tid >> 7) * 64; // j chunk for l-pass

    for (int jt = 0; jt < NN; jt += TJ) {
        __syncthreads();   // previous GEMM done before overwriting tiles
        // hs tile [TJ][COUT]
        {
            const float4* src = (const float4*)(g_hs + ((size_t)(bh * NN + jt)) * COUT);
            float4* dst = (float4*)sHS;
            #pragma unroll
            for (int t = 0; t < 8; t++) dst[tid + t * 256] = src[tid + t * 256];
        }
        if (tid < TJ) ser[tid] = g_er[(size_t)bh * NN + jt + tid];
        __syncthreads();

        // P build: p = adj * exp(leaky(el+er) - m_i), transposed store
        #pragma unroll 4
        for (int t = 0; t < 64; t++) {
            int idx = t * 256 + tid;
            int i = idx >> 7;
            int j = idx & 127;
            float a = __ldg(abase + (size_t)i * NN + jt + j);
            float s = sel[i] + ser[j];
            s = fmaxf(s, 0.1f * s);
            float p = a * __expf(s - selm[i]);
            sP[j * TIP + i] = p;
        }
        __syncthreads();

        // row-sum pass (read-only on sP, no sync needed vs GEMM)
        {
            float s = 0.f;
            #pragma unroll 8
            for (int j = 0; j < 64; j++) s += sP[(ljb + j) * TIP + li];
            lacc += s;
        }

        // O += P @ HS  (FFMA2 packed fp32)
        #pragma unroll 4
        for (int k = 0; k < TJ; k++) {
            const float* pcol = sP + k * TIP + i0;
            unsigned long long q0 = pack2(pcol[0]);
            unsigned long long q1 = pack2(pcol[1]);
            unsigned long long q2 = pack2(pcol[2]);
            unsigned long long q3 = pack2(pcol[3]);
            ulonglong2 h01 = *(const ulonglong2*)(sHS + k * COUT + d0);
            ulonglong2 h23 = *(const ulonglong2*)(sHS + k * COUT + d0 + 4);
            ffma2(acc[0][0], q0, h01.x); ffma2(acc[0][1], q0, h01.y);
            ffma2(acc[0][2], q0, h23.x); ffma2(acc[0][3], q0, h23.y);
            ffma2(acc[1][0], q1, h01.x); ffma2(acc[1][1], q1, h01.y);
            ffma2(acc[1][2], q1, h23.x); ffma2(acc[1][3], q1, h23.y);
            ffma2(acc[2][0], q2, h01.x); ffma2(acc[2][1], q2, h01.y);
            ffma2(acc[2][2], q2, h23.x); ffma2(acc[2][3], q2, h23.y);
            ffma2(acc[3][0], q3, h01.x); ffma2(acc[3][1], q3, h01.y);
            ffma2(acc[3][2], q3, h23.x); ffma2(acc[3][3], q3, h23.y);
        }
    }

    // combine l halves, invert
    __syncthreads();
    sred[tid] = lacc;
    __syncthreads();
    if (tid < 128) {
        float l = sred[tid] + sred[tid + 128];
        sl[tid] = (l > 0.f) ? (1.f / l) : 0.f;
    }
    __syncthreads();

    // epilogue: out[b][i][head*64+d] = acc / l
    float* obase = out + ((size_t)(b * NN + it0)) * HD + head * COUT;
    #pragma unroll
    for (int r = 0; r < 4; r++) {
        float inv = sl[i0 + r];
        float2 v0 = unpack2(acc[r][0]);
        float2 v1 = unpack2(acc[r][1]);
        float2 v2 = unpack2(acc[r][2]);
        float2 v3 = unpack2(acc[r][3]);
        float4 w0 = {v0.x * inv, v0.y * inv, v1.x * inv, v1.y * inv};
        float4 w1 = {v2.x * inv, v2.y * inv, v3.x * inv, v3.y * inv};
        float* op = obase + (size_t)(i0 + r) * HD + d0;
        *(float4*)op = w0;
        *(float4*)(op + 4) = w1;
    }
}

static const int SMEM_K2 = (TJ * TIP + TJ * COUT + TI * 4 + 256) * (int)sizeof(float);

extern "C" void kernel_launch(void* const* d_in, const int* in_sizes, int n_in,
                              void* d_out, int out_size) {
    const float* xs   = (const float*)d_in[0];
    const float* adjs = (const float*)d_in[1];
    const float* W1   = (const float*)d_in[2];
    const float* a_l  = (const float*)d_in[3];
    const float* a_r  = (const float*)d_in[4];
    float* out = (float*)d_out;

    cudaFuncSetAttribute(k2_attn, cudaFuncAttributeMaxDynamicSharedMemorySize, SMEM_K2);

    k1_gemm<<<dim3(32, 4, 4), 256>>>(xs, W1, a_l, a_r);
    k1b_max<<<16, 256>>>();
    k2_attn<<<dim3(16, 4, 4), 256, SMEM_K2>>>(adjs, out);
}

// round 4
// speedup vs baseline: 2.6287x; 2.6287x over previous
#include <cuda_runtime.h>
#include <cstdint>

#define BS   4
#define NN   2048
#define CIN  128
#define COUT 64
#define H    4
#define HD   256
#define TI   128
#define TJ   64
#define JH   1024
#define NJT  16

// device scratch (allocation-free)
__device__ float g_hs[(size_t)BS * H * NN * COUT];   // [bh][n][d], tf32-rounded
__device__ float g_el[BS * H * NN];
__device__ float g_er[BS * H * NN];
__device__ float g_emax[BS * H];
__device__ float g_opart[2][(size_t)BS * NN * HD];
__device__ float g_lpart[2][BS * H * NN];

#define SP_STRIDE 68
#define SH_STRIDE 72
#define OFF_P    0
#define OFF_HS   (2 * TI * SP_STRIDE)            // 17408
#define OFF_ADJ  (OFF_HS + 2 * TJ * SH_STRIDE)   // 26624
#define OFF_ER   (OFF_ADJ + TI * SP_STRIDE)      // 35328
#define SMEM_FLOATS (OFF_ER + 64)                // 35392
#define SMEM_K2  (SMEM_FLOATS * 4)               // 141568 B

__device__ __forceinline__ float rn_tf32(float x) {
    uint32_t u;
    asm("cvt.rn.tf32.f32 %0, %1;" : "=r"(u) : "f"(x));
    return __uint_as_float(u);
}
__device__ __forceinline__ void mma_tf32(float* d, const uint32_t* a, const uint32_t* b) {
    asm volatile(
        "mma.sync.aligned.m16n8k8.row.col.f32.tf32.tf32.f32 "
        "{%0,%1,%2,%3}, {%4,%5,%6,%7}, {%8,%9}, {%0,%1,%2,%3};"
        : "+f"(d[0]), "+f"(d[1]), "+f"(d[2]), "+f"(d[3])
        : "r"(a[0]), "r"(a[1]), "r"(a[2]), "r"(a[3]), "r"(b[0]), "r"(b[1]));
}
#define BARS(id, n) asm volatile("bar.sync %0, %1;" :: "r"(id), "r"(n) : "memory")
#define BARA(id, n) asm volatile("bar.arrive %0, %1;" :: "r"(id), "r"(n) : "memory")

// ---------------- K1: hs = xs @ W1 (tf32-rounded), el/er ----------------
__global__ __launch_bounds__(256) void k1_gemm(const float* __restrict__ xs,
                                               const float* __restrict__ W1,
                                               const float* __restrict__ a_l,
                                               const float* __restrict__ a_r) {
    const int bx = blockIdx.x, head = blockIdx.y, b = blockIdx.z;
    const int tid = threadIdx.x;
    const int ig = tid >> 4, cg = tid & 15;
    const int r0 = ig * 4, c0 = cg * 4;

    __shared__ float As[32][68];
    __shared__ float Bs[32][68];
    __shared__ float sred[16][64];

    float acc[4][4] = {};
    const float* xbase = xs + ((size_t)(b * NN + bx * 64)) * CIN;
    const float* wbase = W1 + head * COUT;

    for (int kc = 0; kc < CIN; kc += 32) {
        int lin = tid;
        #pragma unroll
        for (int t = 0; t < 2; t++, lin += 256) {
            int r = lin >> 3, k4 = lin & 7;
            float4 v = *(const float4*)(xbase + r * CIN + kc + k4 * 4);
            As[k4 * 4 + 0][r] = v.x; As[k4 * 4 + 1][r] = v.y;
            As[k4 * 4 + 2][r] = v.z; As[k4 * 4 + 3][r] = v.w;
        }
        lin = tid;
        #pragma unroll
        for (int t = 0; t < 2; t++, lin += 256) {
            int k = lin >> 4, c4 = lin & 15;
            float4 v = *(const float4*)(wbase + (size_t)(kc + k) * HD + c4 * 4);
            *(float4*)&Bs[k][c4 * 4] = v;
        }
        __syncthreads();
        #pragma unroll
        for (int k = 0; k < 32; k++) {
            float4 aq = *(const float4*)&As[k][r0];
            float4 bq = *(const float4*)&Bs[k][c0];
            float ar[4] = {aq.x, aq.y, aq.z, aq.w};
            float br[4] = {bq.x, bq.y, bq.z, bq.w};
            #pragma unroll
            for (int r = 0; r < 4; r++)
                #pragma unroll
                for (int c = 0; c < 4; c++) acc[r][c] += ar[r] * br[c];
        }
        __syncthreads();
    }

    const int bh = b * H + head;
    #pragma unroll
    for (int r = 0; r < 4; r++) {
        float4 w = {rn_tf32(acc[r][0]), rn_tf32(acc[r][1]),
                    rn_tf32(acc[r][2]), rn_tf32(acc[r][3])};
        *(float4*)(g_hs + ((size_t)(bh * NN + bx * 64 + r0 + r)) * COUT + c0) = w;
    }
    float pl[4] = {}, pr[4] = {};
    #pragma unroll
    for (int r = 0; r < 4; r++)
        #pragma unroll
        for (int c = 0; c < 4; c++) {
            pl[r] += acc[r][c] * __ldg(a_l + c0 + c);
            pr[r] += acc[r][c] * __ldg(a_r + c0 + c);
        }
    #pragma unroll
    for (int r = 0; r < 4; r++) sred[cg][r0 + r] = pl[r];
    __syncthreads();
    if (tid < 64) {
        float s = 0.f;
        #pragma unroll
        for (int g = 0; g < 16; g++) s += sred[g][tid];
        g_el[(size_t)bh * NN + bx * 64 + tid] = s;
    }
    __syncthreads();
    #pragma unroll
    for (int r = 0; r < 4; r++) sred[cg][r0 + r] = pr[r];
    __syncthreads();
    if (tid < 64) {
        float s = 0.f;
        #pragma unroll
        for (int g = 0; g < 16; g++) s += sred[g][tid];
        g_er[(size_t)bh * NN + bx * 64 + tid] = s;
    }
}

// ---------------- K1b: emax ----------------
__global__ void k1b_max() {
    const int bh = blockIdx.x;
    __shared__ float sm[256];
    float m = -1e30f;
    for (int i = threadIdx.x; i < NN; i += 256)
        m = fmaxf(m, g_er[(size_t)bh * NN + i]);
    sm[threadIdx.x] = m;
    __syncthreads();
    for (int s = 128; s > 0; s >>= 1) {
        if (threadIdx.x < s) sm[threadIdx.x] = fmaxf(sm[threadIdx.x], sm[threadIdx.x + s]);
        __syncthreads();
    }
    if (threadIdx.x == 0) g_emax[bh] = sm[0];
}

// ---------------- K2: warp-specialized mma.sync tf32 flash loop ----------------
// warps 0-3: MMA consumers (warp tile 32 rows x 64 cols)
// warps 4-7: builders (thread bt owns P row bt)
// barriers: 1+buf = buffer full, 3+buf = buffer free, 5 = builder-internal
__global__ __launch_bounds__(256, 1) void k2_attn(const float* __restrict__ adjs) {
    extern __shared__ float sm[];
    float* sEr  = sm + OFF_ER;
    float* sAdj = sm + OFF_ADJ;
    const int tid = threadIdx.x, wid = tid >> 5, lane = tid & 31;
    const int i0 = blockIdx.x * TI, half = blockIdx.y, b = blockIdx.z;

    if (wid >= 4) {
        // ---------------- builder ----------------
        const int bt = tid & 127;
        for (int h = 0; h < H; h++) {
            const int bh = b * H + h;
            const float el = g_el[(size_t)bh * NN + i0 + bt];
            const float E = g_emax[bh];
            float t0 = el + E;
            const float m = fmaxf(t0, 0.1f * t0);
            float racc = 0.f;
            const float* hb = g_hs + (size_t)bh * NN * COUT;
            for (int jt = 0; jt < NJT; jt++) {
                const int g = h * NJT + jt, buf = g & 1;
                const int jbase = half * JH + jt * TJ;
                if (g >= 2) BARS(3 + buf, 256);   // wait consumers freed this buffer
                // stage adj tile [128][64] (coalesced)
                const float* ap = adjs + ((size_t)(b * NN + i0)) * NN + jbase;
                #pragma unroll
                for (int v = 0; v < 16; v++) {
                    int idx = bt + v * 128;
                    int r = idx >> 4, c4 = idx & 15;
                    float4 x = *(const float4*)(ap + (size_t)r * NN + c4 * 4);
                    *(float4*)(sAdj + r * SP_STRIDE + c4 * 4) = x;
                }
                // stage HS tile [64][64]
                float* sH = sm + OFF_HS + buf * TJ * SH_STRIDE;
                #pragma unroll
                for (int v = 0; v < 8; v++) {
                    int idx = bt + v * 128;
                    int j = idx >> 4, d4 = idx & 15;
                    float4 x = *(const float4*)(hb + (size_t)(jbase + j) * COUT + d4 * 4);
                    *(float4*)(sH + j * SH_STRIDE + d4 * 4) = x;
                }
                if (bt < 64) sEr[bt] = g_er[(size_t)bh * NN + jbase + bt];
                BARS(5, 128);
                // build P row bt
                float* sPb = sm + OFF_P + buf * TI * SP_STRIDE;
                float rs = 0.f;
                #pragma unroll
                for (int q = 0; q < 16; q++) {
                    float4 a4 = *(const float4*)(sAdj + bt * SP_STRIDE + q * 4);
                    float4 e4 = *(const float4*)(sEr + q * 4);
                    const float* av = (const float*)&a4;
                    const float* ev = (const float*)&e4;
                    float p[4];
                    #pragma unroll
                    for (int e = 0; e < 4; e++) {
                        float s = el + ev[e];
                        s = fmaxf(s, 0.1f * s);
                        float pe = av[e] * __expf(s - m);
                        rs += pe;
                        p[e] = rn_tf32(pe);
                    }
                    *(float4*)(sPb + bt * SP_STRIDE + q * 4) = *(const float4*)p;
                }
                racc += rs;
                BARS(5, 128);       // build done: safe to restage sAdj/sEr next iter
                BARA(1 + buf, 256); // publish buffer full
            }
            g_lpart[half][(size_t)bh * NN + i0 + bt] = racc;
        }
    } else {
        // ---------------- consumer ----------------
        const int gid = lane >> 2, tg = lane & 3;
        for (int h = 0; h < H; h++) {
            float acc[2][8][4];
            #pragma unroll
            for (int mr = 0; mr < 2; mr++)
                #pragma unroll
                for (int nc = 0; nc < 8; nc++)
                    #pragma unroll
                    for (int e = 0; e < 4; e++) acc[mr][nc][e] = 0.f;
            for (int jt = 0; jt < NJT; jt++) {
                const int g = h * NJT + jt, buf = g & 1;
                BARS(1 + buf, 256);   // wait buffer full
                const float* sPb = sm + OFF_P + buf * TI * SP_STRIDE;
                const float* sH  = sm + OFF_HS + buf * TJ * SH_STRIDE;
                #pragma unroll
                for (int ks = 0; ks < 8; ks++) {
                    const int k0 = ks * 8;
                    uint32_t a[2][4], bb[8][2];
                    #pragma unroll
                    for (int mr = 0; mr < 2; mr++) {
                        const float* pa = sPb + (wid * 32 + mr * 16 + gid) * SP_STRIDE + k0 + tg;
                        a[mr][0] = __float_as_uint(pa[0]);
                        a[mr][1] = __float_as_uint(pa[8 * SP_STRIDE]);
                        a[mr][2] = __float_as_uint(pa[4]);
                        a[mr][3] = __float_as_uint(pa[8 * SP_STRIDE + 4]);
                    }
                    #pragma unroll
                    for (int nc = 0; nc < 8; nc++) {
                        const float* pb = sH + (k0 + tg) * SH_STRIDE + nc * 8 + gid;
                        bb[nc][0] = __float_as_uint(pb[0]);
                        bb[nc][1] = __float_as_uint(pb[4 * SH_STRIDE]);
                    }
                    #pragma unroll
                    for (int mr = 0; mr < 2; mr++)
                        #pragma unroll
                        for (int nc = 0; nc < 8; nc++)
                            mma_tf32(acc[mr][nc], a[mr], bb[nc]);
                }
                BARA(3 + buf, 256);   // buffer free
            }
            // epilogue head h: write unnormalized partial O
            float* ob = g_opart[half] + ((size_t)b * NN) * HD;
            #pragma unroll
            for (int mr = 0; mr < 2; mr++) {
                int rlo = i0 + wid * 32 + mr * 16 + gid;
                #pragma unroll
                for (int nc = 0; nc < 8; nc++) {
                    int col = h * 64 + nc * 8 + 2 * tg;
                    float2 v0 = {acc[mr][nc][0], acc[mr][nc][1]};
                    float2 v1 = {acc[mr][nc][2], acc[mr][nc][3]};
                    *(float2*)(ob + (size_t)rlo * HD + col) = v0;
                    *(float2*)(ob + (size_t)(rlo + 8) * HD + col) = v1;
                }
            }
        }
    }
}

// ---------------- K3: combine halves + normalize ----------------
__global__ __launch_bounds__(256) void k3_combine(float* __restrict__ out) {
    int idx = blockIdx.x * 256 + threadIdx.x;
    size_t flat = (size_t)idx * 4;
    int b   = (int)(flat / ((size_t)NN * HD));
    int rem = (int)(flat % ((size_t)NN * HD));
    int i = rem / HD;
    int h = (rem % HD) >> 6;
    size_t li = (size_t)(b * H + h) * NN + i;
    float l = g_lpart[0][li] + g_lpart[1][li];
    float inv = (l > 0.f) ? (1.f / l) : 0.f;
    float4 o0 = *(const float4*)(g_opart[0] + flat);
    float4 o1 = *(const float4*)(g_opart[1] + flat);
    float4 w = {(o0.x + o1.x) * inv, (o0.y + o1.y) * inv,
                (o0.z + o1.z) * inv, (o0.w + o1.w) * inv};
    *(float4*)(out + flat) = w;
}

extern "C" void kernel_launch(void* const* d_in, const int* in_sizes, int n_in,
                              void* d_out, int out_size) {
    const float* xs   = (const float*)d_in[0];
    const float* adjs = (const float*)d_in[1];
    const float* W1   = (const float*)d_in[2];
    const float* a_l  = (const float*)d_in[3];
    const float* a_r  = (const float*)d_in[4];
    float* out = (float*)d_out;

    cudaFuncSetAttribute(k2_attn, cudaFuncAttributeMaxDynamicSharedMemorySize, SMEM_K2);

    k1_gemm<<<dim3(32, 4, 4), 256>>>(xs, W1, a_l, a_r);
    k1b_max<<<16, 256>>>();
    k2_attn<<<dim3(16, 2, 4), 256, SMEM_K2>>>(adjs);
    k3_combine<<<(BS * NN * HD / 4) / 256, 256>>>(out);
}

// round 5
// speedup vs baseline: 3.0139x; 1.1466x over previous
#include <cuda_runtime.h>
#include <cstdint>

#define BS   4
#define NN   2048
#define CIN  128
#define COUT 64
#define H    4
#define HD   256
#define TI   64
#define TJ   64
#define JH   1024
#define NJT  16

// device scratch (allocation-free)
__device__ float g_hs[(size_t)BS * H * NN * COUT];   // [bh][n][d], tf32-rounded
__device__ float g_el[BS * H * NN];
__device__ float g_er[BS * H * NN];
__device__ float g_emax[BS * H];
__device__ float g_opart[2][(size_t)BS * NN * HD];
__device__ float g_lpart[2][BS * H * NN];

#define SP_STRIDE 68
#define SH_STRIDE 72
// smem float offsets
#define OFF_P    0                         // 2 x 64 x 68 = 8704
#define OFF_HS   8704                      // 2 x 64 x 72 = 9216
#define OFF_ER   17920                     // 2 x 64
#define OFF_EL   18048                     // 64
#define OFF_M    18112                     // 64
#define SMEM_FLOATS 18176
#define SMEM_K2  (SMEM_FLOATS * 4)         // 72704 B

__device__ __forceinline__ float rn_tf32(float x) {
    uint32_t u;
    asm("cvt.rn.tf32.f32 %0, %1;" : "=r"(u) : "f"(x));
    return __uint_as_float(u);
}
__device__ __forceinline__ void mma_tf32(float* d, const uint32_t* a, const uint32_t* b) {
    asm volatile(
        "mma.sync.aligned.m16n8k8.row.col.f32.tf32.tf32.f32 "
        "{%0,%1,%2,%3}, {%4,%5,%6,%7}, {%8,%9}, {%0,%1,%2,%3};"
        : "+f"(d[0]), "+f"(d[1]), "+f"(d[2]), "+f"(d[3])
        : "r"(a[0]), "r"(a[1]), "r"(a[2]), "r"(a[3]), "r"(b[0]), "r"(b[1]));
}
#define BARS(id, n) asm volatile("bar.sync %0, %1;" :: "r"(id), "r"(n) : "memory")
#define BARA(id, n) asm volatile("bar.arrive %0, %1;" :: "r"(id), "r"(n) : "memory")

// ---------------- K1: hs = xs @ W1 (tf32-rounded), el/er ----------------
__global__ __launch_bounds__(256) void k1_gemm(const float* __restrict__ xs,
                                               const float* __restrict__ W1,
                                               const float* __restrict__ a_l,
                                               const float* __restrict__ a_r) {
    const int bx = blockIdx.x, head = blockIdx.y, b = blockIdx.z;
    const int tid = threadIdx.x;
    const int ig = tid >> 4, cg = tid & 15;
    const int r0 = ig * 4, c0 = cg * 4;

    __shared__ float As[32][68];
    __shared__ float Bs[32][68];
    __shared__ float sred[16][64];

    float acc[4][4] = {};
    const float* xbase = xs + ((size_t)(b * NN + bx * 64)) * CIN;
    const float* wbase = W1 + head * COUT;

    for (int kc = 0; kc < CIN; kc += 32) {
        int lin = tid;
        #pragma unroll
        for (int t = 0; t < 2; t++, lin += 256) {
            int r = lin >> 3, k4 = lin & 7;
            float4 v = *(const float4*)(xbase + r * CIN + kc + k4 * 4);
            As[k4 * 4 + 0][r] = v.x; As[k4 * 4 + 1][r] = v.y;
            As[k4 * 4 + 2][r] = v.z; As[k4 * 4 + 3][r] = v.w;
        }
        lin = tid;
        #pragma unroll
        for (int t = 0; t < 2; t++, lin += 256) {
            int k = lin >> 4, c4 = lin & 15;
            float4 v = *(const float4*)(wbase + (size_t)(kc + k) * HD + c4 * 4);
            *(float4*)&Bs[k][c4 * 4] = v;
        }
        __syncthreads();
        #pragma unroll
        for (int k = 0; k < 32; k++) {
            float4 aq = *(const float4*)&As[k][r0];
            float4 bq = *(const float4*)&Bs[k][c0];
            float ar[4] = {aq.x, aq.y, aq.z, aq.w};
            float br[4] = {bq.x, bq.y, bq.z, bq.w};
            #pragma unroll
            for (int r = 0; r < 4; r++)
                #pragma unroll
                for (int c = 0; c < 4; c++) acc[r][c] += ar[r] * br[c];
        }
        __syncthreads();
    }

    const int bh = b * H + head;
    #pragma unroll
    for (int r = 0; r < 4; r++) {
        float4 w = {rn_tf32(acc[r][0]), rn_tf32(acc[r][1]),
                    rn_tf32(acc[r][2]), rn_tf32(acc[r][3])};
        *(float4*)(g_hs + ((size_t)(bh * NN + bx * 64 + r0 + r)) * COUT + c0) = w;
    }
    float pl[4] = {}, pr[4] = {};
    #pragma unroll
    for (int r = 0; r < 4; r++)
        #pragma unroll
        for (int c = 0; c < 4; c++) {
            pl[r] += acc[r][c] * __ldg(a_l + c0 + c);
            pr[r] += acc[r][c] * __ldg(a_r + c0 + c);
        }
    #pragma unroll
    for (int r = 0; r < 4; r++) sred[cg][r0 + r] = pl[r];
    __syncthreads();
    if (tid < 64) {
        float s = 0.f;
        #pragma unroll
        for (int g = 0; g < 16; g++) s += sred[g][tid];
        g_el[(size_t)bh * NN + bx * 64 + tid] = s;
    }
    __syncthreads();
    #pragma unroll
    for (int r = 0; r < 4; r++) sred[cg][r0 + r] = pr[r];
    __syncthreads();
    if (tid < 64) {
        float s = 0.f;
        #pragma unroll
        for (int g = 0; g < 16; g++) s += sred[g][tid];
        g_er[(size_t)bh * NN + bx * 64 + tid] = s;
    }
}

// ---------------- K1b: emax ----------------
__global__ void k1b_max() {
    const int bh = blockIdx.x;
    __shared__ float sm[256];
    float m = -1e30f;
    for (int i = threadIdx.x; i < NN; i += 256)
        m = fmaxf(m, g_er[(size_t)bh * NN + i]);
    sm[threadIdx.x] = m;
    __syncthreads();
    for (int s = 128; s > 0; s >>= 1) {
        if (threadIdx.x < s) sm[threadIdx.x] = fmaxf(sm[threadIdx.x], sm[threadIdx.x + s]);
        __syncthreads();
    }
    if (threadIdx.x == 0) g_emax[bh] = sm[0];
}

// ---------------- K2: warp-specialized mma.sync tf32, l via ones-column ----------------
// warps 0-3: MMA consumers (warp tile 16 rows x 72 cols; col 64 = row sum)
// warps 4-7: builders (direct adj LDG -> P STS)
// barriers: 1+buf full, 3+buf free, 5 builder-internal
__global__ __launch_bounds__(256, 2) void k2_attn(const float* __restrict__ adjs) {
    extern __shared__ float sm[];
    const int tid = threadIdx.x, wid = tid >> 5, lane = tid & 31;
    const int i0 = blockIdx.x * TI, half = blockIdx.y, b = blockIdx.z;

    // init ones-columns of both HS buffers (cols 64..71), done once
    for (int idx = tid; idx < 2 * 64 * 8; idx += 256) {
        int buf = idx >> 9, rem = idx & 511;
        int j = rem >> 3, c = rem & 7;
        sm[OFF_HS + buf * 64 * SH_STRIDE + j * SH_STRIDE + 64 + c] = (c == 0) ? 1.f : 0.f;
    }
    __syncthreads();

    if (wid >= 4) {
        // ---------------- builder ----------------
        const int bt = tid & 127;
        const int c4 = bt & 15;          // col group (4 cols)
        const int rb = bt >> 4;          // row base (0..7), rows rb + 8v
        for (int h = 0; h < H; h++) {
            const int bh = b * H + h;
            const float* hb = g_hs + (size_t)bh * NN * COUT;
            for (int jt = 0; jt < NJT; jt++) {
                const int g = h * NJT + jt, buf = g & 1;
                const int jbase = half * JH + jt * TJ;
                if (g >= 2) BARS(3 + buf, 256);     // consumers freed this buffer
                BARS(5, 128);                       // all builders done previous build
                // stage HS tile [64][64]
                float* sH = sm + OFF_HS + buf * 64 * SH_STRIDE;
                #pragma unroll
                for (int v = 0; v < 8; v++) {
                    int idx = bt + v * 128;
                    int j = idx >> 4, d4 = idx & 15;
                    float4 x = *(const float4*)(hb + (size_t)(jbase + j) * COUT + d4 * 4);
                    *(float4*)(sH + j * SH_STRIDE + d4 * 4) = x;
                }
                if (bt < 64) sm[OFF_ER + buf * 64 + bt] = g_er[(size_t)bh * NN + jbase + bt];
                if (jt == 0 && bt < 64) {
                    float e = g_el[(size_t)bh * NN + i0 + bt];
                    sm[OFF_EL + bt] = e;
                    float t = e + g_emax[bh];
                    sm[OFF_M + bt] = fmaxf(t, 0.1f * t);
                }
                BARS(5, 128);
                // build P: direct adj LDG -> compute -> STS
                float4 aj[8];
                const float* ap = adjs + ((size_t)(b * NN + i0 + rb)) * NN + jbase + c4 * 4;
                #pragma unroll
                for (int v = 0; v < 8; v++)
                    aj[v] = *(const float4*)(ap + (size_t)(v * 8) * NN);
                float4 er4 = *(const float4*)(sm + OFF_ER + buf * 64 + c4 * 4);
                const float* erv = (const float*)&er4;
                float* sPb = sm + OFF_P + buf * 64 * SP_STRIDE;
                #pragma unroll
                for (int v = 0; v < 8; v++) {
                    int r = rb + v * 8;
                    float el = sm[OFF_EL + r];
                    float m  = sm[OFF_M + r];
                    const float* av = (const float*)&aj[v];
                    float p[4];
                    #pragma unroll
                    for (int e = 0; e < 4; e++) {
                        float s = el + erv[e];
                        s = fmaxf(s, 0.1f * s);
                        float pe = av[e] * __expf(s - m);
                        p[e] = rn_tf32(pe);
                    }
                    *(float4*)(sPb + r * SP_STRIDE + c4 * 4) = *(const float4*)p;
                }
                BARA(1 + buf, 256);                 // publish full
            }
        }
    } else {
        // ---------------- consumer ----------------
        const int gid = lane >> 2, tg = lane & 3;
        for (int h = 0; h < H; h++) {
            const int bh = b * H + h;
            float acc[9][4];
            #pragma unroll
            for (int nc = 0; nc < 9; nc++)
                #pragma unroll
                for (int e = 0; e < 4; e++) acc[nc][e] = 0.f;
            for (int jt = 0; jt < NJT; jt++) {
                const int g = h * NJT + jt, buf = g & 1;
                BARS(1 + buf, 256);
                const float* sPb = sm + OFF_P + buf * 64 * SP_STRIDE;
                const float* sH  = sm + OFF_HS + buf * 64 * SH_STRIDE;
                #pragma unroll
                for (int ks = 0; ks < 8; ks++) {
                    const int k0 = ks * 8;
                    uint32_t a[4], bb[9][2];
                    const float* pa = sPb + (wid * 16 + gid) * SP_STRIDE + k0 + tg;
                    a[0] = __float_as_uint(pa[0]);
                    a[1] = __float_as_uint(pa[8 * SP_STRIDE]);
                    a[2] = __float_as_uint(pa[4]);
                    a[3] = __float_as_uint(pa[8 * SP_STRIDE + 4]);
                    #pragma unroll
                    for (int nc = 0; nc < 9; nc++) {
                        const float* pb = sH + (k0 + tg) * SH_STRIDE + nc * 8 + gid;
                        bb[nc][0] = __float_as_uint(pb[0]);
                        bb[nc][1] = __float_as_uint(pb[4 * SH_STRIDE]);
                    }
                    #pragma unroll
                    for (int nc = 0; nc < 9; nc++)
                        mma_tf32(acc[nc], a, bb[nc]);
                }
                BARA(3 + buf, 256);
            }
            // epilogue: unnormalized O + l (col 64)
            const int r0 = i0 + wid * 16 + gid;
            float* ob = g_opart[half] + ((size_t)b * NN) * HD;
            #pragma unroll
            for (int nc = 0; nc < 8; nc++) {
                int col = h * 64 + nc * 8 + 2 * tg;
                float2 v0 = {acc[nc][0], acc[nc][1]};
                float2 v1 = {acc[nc][2], acc[nc][3]};
                *(float2*)(ob + (size_t)r0 * HD + col) = v0;
                *(float2*)(ob + (size_t)(r0 + 8) * HD + col) = v1;
            }
            if (tg == 0) {
                g_lpart[half][(size_t)bh * NN + r0] = acc[8][0];
                g_lpart[half][(size_t)bh * NN + r0 + 8] = acc[8][2];
            }
        }
    }
}

// ---------------- K3: combine halves + normalize ----------------
__global__ __launch_bounds__(256) void k3_combine(float* __restrict__ out) {
    int idx = blockIdx.x * 256 + threadIdx.x;
    size_t flat = (size_t)idx * 4;
    int b   = (int)(flat / ((size_t)NN * HD));
    int rem = (int)(flat % ((size_t)NN * HD));
    int i = rem / HD;
    int h = (rem % HD) >> 6;
    size_t li = (size_t)(b * H + h) * NN + i;
    float l = g_lpart[0][li] + g_lpart[1][li];
    float inv = (l > 0.f) ? (1.f / l) : 0.f;
    float4 o0 = *(const float4*)(g_opart[0] + flat);
    float4 o1 = *(const float4*)(g_opart[1] + flat);
    float4 w = {(o0.x + o1.x) * inv, (o0.y + o1.y) * inv,
                (o0.z + o1.z) * inv, (o0.w + o1.w) * inv};
    *(float4*)(out + flat) = w;
}

extern "C" void kernel_launch(void* const* d_in, const int* in_sizes, int n_in,
                              void* d_out, int out_size) {
    const float* xs   = (const float*)d_in[0];
    const float* adjs = (const float*)d_in[1];
    const float* W1   = (const float*)d_in[2];
    const float* a_l  = (const float*)d_in[3];
    const float* a_r  = (const float*)d_in[4];
    float* out = (float*)d_out;

    cudaFuncSetAttribute(k2_attn, cudaFuncAttributeMaxDynamicSharedMemorySize, SMEM_K2);

    k1_gemm<<<dim3(32, 4, 4), 256>>>(xs, W1, a_l, a_r);
    k1b_max<<<16, 256>>>();
    k2_attn<<<dim3(32, 2, 4), 256, SMEM_K2>>>(adjs);
    k3_combine<<<(BS * NN * HD / 4) / 256, 256>>>(out);
}

// round 6
// speedup vs baseline: 3.3834x; 1.1226x over previous
#include <cuda_runtime.h>
#include <cstdint>

#define BS   4
#define NN   2048
#define CIN  128
#define COUT 64
#define H    4
#define HD   256
#define TI   64
#define TJ   64
#define JH   1024
#define NJT  16
#define LOG2E 1.4426950408889634f

// device scratch (allocation-free)
__device__ float g_hst[(size_t)BS * H * COUT * NN];   // [bh][d][n], tf32-rounded
__device__ float g_el[BS * H * NN];                   // pre-scaled by log2e
__device__ float g_er[BS * H * NN];                   // pre-scaled by log2e
__device__ float g_emax[BS * H];
__device__ float g_opart[2][(size_t)BS * NN * HD];
__device__ float g_lpart[2][BS * H * NN];

// K2 smem layout (floats)
#define SP_STRIDE 68
#define PBUF   4352              // 64*68
#define HBUF   4896              // 72*68 (rows 64..71 = ones-block)
#define OFF_HS 8704              // after 2 P buffers
#define OFF_ER 18496
#define OFF_EL 18624
#define OFF_M  18880
#define SMEM_FLOATS 19136
#define SMEM_K2 (SMEM_FLOATS * 4)   // 76544 B
#define PBUF_B  17408
#define HBUF_B  19584
#define OFF_HS_B 34816

__device__ __forceinline__ uint32_t smem_u32(const void* p) {
    uint32_t a;
    asm("{ .reg .u64 t; cvta.to.shared.u64 t, %1; cvt.u32.u64 %0, t; }" : "=r"(a) : "l"(p));
    return a;
}
__device__ __forceinline__ float rn_tf32(float x) {
    uint32_t u;
    asm("cvt.rn.tf32.f32 %0, %1;" : "=r"(u) : "f"(x));
    return __uint_as_float(u);
}
__device__ __forceinline__ float ex2f(float x) {
    float r;
    asm("ex2.approx.f32 %0, %1;" : "=f"(r) : "f"(x));
    return r;
}
__device__ __forceinline__ void mma_tf32(float* d, const uint32_t* a, const uint32_t* b) {
    asm volatile(
        "mma.sync.aligned.m16n8k8.row.col.f32.tf32.tf32.f32 "
        "{%0,%1,%2,%3}, {%4,%5,%6,%7}, {%8,%9}, {%0,%1,%2,%3};"
        : "+f"(d[0]), "+f"(d[1]), "+f"(d[2]), "+f"(d[3])
        : "r"(a[0]), "r"(a[1]), "r"(a[2]), "r"(a[3]), "r"(b[0]), "r"(b[1]));
}
__device__ __forceinline__ void ldsm_x4(uint32_t* r, uint32_t addr) {
    asm volatile("ldmatrix.sync.aligned.m8n8.x4.shared.b16 {%0,%1,%2,%3}, [%4];"
                 : "=r"(r[0]), "=r"(r[1]), "=r"(r[2]), "=r"(r[3]) : "r"(addr));
}
__device__ __forceinline__ void ldsm_x2(uint32_t* r, uint32_t addr) {
    asm volatile("ldmatrix.sync.aligned.m8n8.x2.shared.b16 {%0,%1}, [%2];"
                 : "=r"(r[0]), "=r"(r[1]) : "r"(addr));
}
__device__ __forceinline__ void cp16(uint32_t dst, const void* src) {
    asm volatile("cp.async.ca.shared.global [%0], [%1], 16;" :: "r"(dst), "l"(src));
}
#define CP_COMMIT asm volatile("cp.async.commit_group;" ::: "memory")
#define CP_WAIT0  asm volatile("cp.async.wait_group 0;" ::: "memory")
#define BARS(id, n) asm volatile("bar.sync %0, %1;" :: "r"(id), "r"(n) : "memory")
#define BARA(id, n) asm volatile("bar.arrive %0, %1;" :: "r"(id), "r"(n) : "memory")

// ---------------- K1: hs = xs @ W1 -> g_hst (transposed, tf32), scaled el/er ----------------
__global__ __launch_bounds__(256) void k1_gemm(const float* __restrict__ xs,
                                               const float* __restrict__ W1,
                                               const float* __restrict__ a_l,
                                               const float* __restrict__ a_r) {
    const int bx = blockIdx.x, head = blockIdx.y, b = blockIdx.z;
    const int tid = threadIdx.x;
    const int ig = tid >> 4, cg = tid & 15;
    const int r0 = ig * 4, c0 = cg * 4;

    __shared__ float As[32][68];
    __shared__ float Bs[32][68];
    __shared__ float sred[16][64];

    float acc[4][4] = {};
    const float* xbase = xs + ((size_t)(b * NN + bx * 64)) * CIN;
    const float* wbase = W1 + head * COUT;

    for (int kc = 0; kc < CIN; kc += 32) {
        int lin = tid;
        #pragma unroll
        for (int t = 0; t < 2; t++, lin += 256) {
            int r = lin >> 3, k4 = lin & 7;
            float4 v = *(const float4*)(xbase + r * CIN + kc + k4 * 4);
            As[k4 * 4 + 0][r] = v.x; As[k4 * 4 + 1][r] = v.y;
            As[k4 * 4 + 2][r] = v.z; As[k4 * 4 + 3][r] = v.w;
        }
        lin = tid;
        #pragma unroll
        for (int t = 0; t < 2; t++, lin += 256) {
            int k = lin >> 4, c4 = lin & 15;
            float4 v = *(const float4*)(wbase + (size_t)(kc + k) * HD + c4 * 4);
            *(float4*)&Bs[k][c4 * 4] = v;
        }
        __syncthreads();
        #pragma unroll
        for (int k = 0; k < 32; k++) {
            float4 aq = *(const float4*)&As[k][r0];
            float4 bq = *(const float4*)&Bs[k][c0];
            float ar[4] = {aq.x, aq.y, aq.z, aq.w};
            float br[4] = {bq.x, bq.y, bq.z, bq.w};
            #pragma unroll
            for (int r = 0; r < 4; r++)
                #pragma unroll
                for (int c = 0; c < 4; c++) acc[r][c] += ar[r] * br[c];
        }
        __syncthreads();
    }

    const int bh = b * H + head;
    // transposed tf32 store: g_hst[bh][d][n]
    #pragma unroll
    for (int c = 0; c < 4; c++) {
        float4 w = {rn_tf32(acc[0][c]), rn_tf32(acc[1][c]),
                    rn_tf32(acc[2][c]), rn_tf32(acc[3][c])};
        *(float4*)(g_hst + ((size_t)(bh * COUT + c0 + c)) * NN + bx * 64 + r0) = w;
    }
    float pl[4] = {}, pr[4] = {};
    #pragma unroll
    for (int r = 0; r < 4; r++)
        #pragma unroll
        for (int c = 0; c < 4; c++) {
            pl[r] += acc[r][c] * __ldg(a_l + c0 + c);
            pr[r] += acc[r][c] * __ldg(a_r + c0 + c);
        }
    #pragma unroll
    for (int r = 0; r < 4; r++) sred[cg][r0 + r] = pl[r];
    __syncthreads();
    if (tid < 64) {
        float s = 0.f;
        #pragma unroll
        for (int g = 0; g < 16; g++) s += sred[g][tid];
        g_el[(size_t)bh * NN + bx * 64 + tid] = s * LOG2E;
    }
    __syncthreads();
    #pragma unroll
    for (int r = 0; r < 4; r++) sred[cg][r0 + r] = pr[r];
    __syncthreads();
    if (tid < 64) {
        float s = 0.f;
        #pragma unroll
        for (int g = 0; g < 16; g++) s += sred[g][tid];
        g_er[(size_t)bh * NN + bx * 64 + tid] = s * LOG2E;
    }
}

// ---------------- K1b: emax (on scaled er) ----------------
__global__ void k1b_max() {
    const int bh = blockIdx.x;
    __shared__ float sm[256];
    float m = -1e30f;
    for (int i = threadIdx.x; i < NN; i += 256)
        m = fmaxf(m, g_er[(size_t)bh * NN + i]);
    sm[threadIdx.x] = m;
    __syncthreads();
    for (int s = 128; s > 0; s >>= 1) {
        if (threadIdx.x < s) sm[threadIdx.x] = fmaxf(sm[threadIdx.x], sm[threadIdx.x + s]);
        __syncthreads();
    }
    if (threadIdx.x == 0) g_emax[bh] = sm[0];
}

// ---------------- K2 builder body ----------------
struct K2Ctx {
    float* sm;
    uint32_t smb;
    const float* adjs;
    int i0, half, b, bt, c4, rb;
};

__device__ __forceinline__ void builder_iter(const K2Ctx& cx, int h, int jt,
                                             float4* cur, float4* nxt) {
    const int g = h * NJT + jt, buf = g & 1;
    const int bh = cx.b * H + h;
    const int jbase = cx.half * JH + jt * TJ;
    // prefetch next adj tile into regs (adj is h-independent; parity continues across h)
    {
        const int jn = cx.half * JH + (((jt + 1) & 15)) * TJ;
        const float* apn = cx.adjs + ((size_t)(cx.b * NN + cx.i0 + cx.rb)) * NN + jn + cx.c4 * 4;
        #pragma unroll
        for (int v = 0; v < 8; v++) nxt[v] = *(const float4*)(apn + (size_t)(v * 8) * NN);
    }
    if (g >= 2) BARS(3 + buf, 256);
    if (cx.bt < 64)
        cx.sm[OFF_ER + buf * 64 + cx.bt] = g_er[(size_t)bh * NN + jbase + cx.bt];
    // cp.async HS tile [64 d][64 j] (transposed source g_hst)
    {
        uint32_t hB = cx.smb + OFF_HS_B + buf * HBUF_B;
        const float* hsrc = g_hst + (size_t)bh * COUT * NN + jbase;
        #pragma unroll
        for (int v = 0; v < 8; v++) {
            int idx = cx.bt + v * 128;
            int d = idx >> 4, j4 = idx & 15;
            cp16(hB + (uint32_t)(d * SP_STRIDE + j4 * 4) * 4, hsrc + (size_t)d * NN + j4 * 4);
        }
        CP_COMMIT;
    }
    BARS(5, 128);   // sEr visible to all builders
    // build P (raw fp32; HW mma truncates to tf32)
    {
        float4 er4 = *(const float4*)(cx.sm + OFF_ER + buf * 64 + cx.c4 * 4);
        const float* erv = (const float*)&er4;
        float* sPb = cx.sm + buf * PBUF;
        #pragma unroll
        for (int v = 0; v < 8; v++) {
            int r = cx.rb + v * 8;
            float el = cx.sm[OFF_EL + h * 64 + r];
            float mm = cx.sm[OFF_M + h * 64 + r];
            const float* av = (const float*)&cur[v];
            float p[4];
            #pragma unroll
            for (int e = 0; e < 4; e++) {
                float t = el + erv[e];
                t = fmaxf(t, 0.1f * t);
                p[e] = av[e] * ex2f(t - mm);
            }
            *(float4*)(sPb + r * SP_STRIDE + cx.c4 * 4) = *(const float4*)p;
        }
    }
    CP_WAIT0;
    BARA(1 + buf, 256);   // publish full
}

// ---------------- K2: warp-specialized mma.sync tf32, ldmatrix + cp.async ----------------
__global__ __launch_bounds__(256, 2) void k2_attn(const float* __restrict__ adjs) {
    extern __shared__ float sm[];
    const uint32_t smb = smem_u32(sm);
    const int tid = threadIdx.x, wid = tid >> 5, lane = tid & 31;
    const int i0 = blockIdx.x * TI, half = blockIdx.y, b = blockIdx.z;

    // init ones-block rows 64..71 of both HS buffers
    for (int idx = tid; idx < 2 * 8 * 64; idx += 256) {
        int buf = idx >> 9, rem = idx & 511;
        int r8 = rem >> 6, c = rem & 63;
        sm[OFF_HS + buf * HBUF + (64 + r8) * SP_STRIDE + c] = (r8 == 0) ? 1.f : 0.f;
    }
    __syncthreads();

    if (wid >= 4) {
        // ---------------- builders ----------------
        K2Ctx cx;
        cx.sm = sm; cx.smb = smb; cx.adjs = adjs;
        cx.i0 = i0; cx.half = half; cx.b = b;
        cx.bt = tid & 127; cx.c4 = cx.bt & 15; cx.rb = cx.bt >> 4;
        // prologue: el / m for all heads (scaled domain)
        for (int idx = cx.bt; idx < 256; idx += 128) {
            int h = idx >> 6, r = idx & 63;
            const int bh = b * H + h;
            float e = g_el[(size_t)bh * NN + i0 + r];
            sm[OFF_EL + idx] = e;
            float t = e + g_emax[bh];
            sm[OFF_M + idx] = fmaxf(t, 0.1f * t);
        }
        // initial adj load (g = 0)
        float4 ajA[8], ajB[8];
        {
            const float* ap0 = adjs + ((size_t)(b * NN + i0 + cx.rb)) * NN + half * JH + cx.c4 * 4;
            #pragma unroll
            for (int v = 0; v < 8; v++) ajA[v] = *(const float4*)(ap0 + (size_t)(v * 8) * NN);
        }
        for (int h = 0; h < H; h++) {
            #pragma unroll 1
            for (int jp = 0; jp < 8; jp++) {
                builder_iter(cx, h, 2 * jp,     ajA, ajB);
                builder_iter(cx, h, 2 * jp + 1, ajB, ajA);
            }
        }
    } else {
        // ---------------- consumers ----------------
        const int gid = lane >> 2, tg = lane & 3;
        const int Lr = lane & 7;
        const uint32_t aOff = (uint32_t)((wid * 16 + ((lane >> 3) & 1) * 8 + Lr) * SP_STRIDE
                                         + (lane >> 4) * 4) * 4;
        const uint32_t bOff = (uint32_t)(((lane >> 4) * 8 + Lr) * SP_STRIDE
                                         + ((lane >> 3) & 1) * 4) * 4;
        const uint32_t oOff = (uint32_t)((64 + Lr) * SP_STRIDE + ((lane >> 3) & 1) * 4) * 4;
        for (int h = 0; h < H; h++) {
            const int bh = b * H + h;
            float acc[9][4];
            #pragma unroll
            for (int nc = 0; nc < 9; nc++)
                #pragma unroll
                for (int e = 0; e < 4; e++) acc[nc][e] = 0.f;
            for (int jt = 0; jt < NJT; jt++) {
                const int g = h * NJT + jt, buf = g & 1;
                BARS(1 + buf, 256);
                uint32_t pA = smb + buf * PBUF_B + aOff;
                uint32_t hAb = smb + OFF_HS_B + buf * HBUF_B;
                uint32_t bA = hAb + bOff;
                uint32_t oA = hAb + oOff;
                #pragma unroll
                for (int ks = 0; ks < 8; ks++) {
                    uint32_t a[4];
                    ldsm_x4(a, pA); pA += 32;
                    #pragma unroll
                    for (int ncp = 0; ncp < 4; ncp++) {
                        uint32_t bb[4];
                        ldsm_x4(bb, bA + (uint32_t)ncp * (16 * SP_STRIDE * 4));
                        mma_tf32(acc[2 * ncp], a, bb);
                        mma_tf32(acc[2 * ncp + 1], a, bb + 2);
                    }
                    bA += 32;
                    uint32_t oo[2];
                    ldsm_x2(oo, oA); oA += 32;
                    mma_tf32(acc[8], a, oo);
                }
                BARA(3 + buf, 256);
            }
            // epilogue: unnormalized O + l (ones block col 0 => acc[8][0]/acc[8][2])
            const int r0 = i0 + wid * 16 + gid;
            float* ob = g_opart[half] + ((size_t)b * NN) * HD;
            #pragma unroll
            for (int nc = 0; nc < 8; nc++) {
                int col = h * 64 + nc * 8 + 2 * tg;
                float2 v0 = {acc[nc][0], acc[nc][1]};
                float2 v1 = {acc[nc][2], acc[nc][3]};
                *(float2*)(ob + (size_t)r0 * HD + col) = v0;
                *(float2*)(ob + (size_t)(r0 + 8) * HD + col) = v1;
            }
            if (tg == 0) {
                g_lpart[half][(size_t)bh * NN + r0] = acc[8][0];
                g_lpart[half][(size_t)bh * NN + r0 + 8] = acc[8][2];
            }
        }
    }
}

// ---------------- K3: combine halves + normalize ----------------
__global__ __launch_bounds__(256) void k3_combine(float* __restrict__ out) {
    int idx = blockIdx.x * 256 + threadIdx.x;
    size_t flat = (size_t)idx * 4;
    int b   = (int)(flat / ((size_t)NN * HD));
    int rem = (int)(flat % ((size_t)NN * HD));
    int i = rem / HD;
    int h = (rem % HD) >> 6;
    size_t li = (size_t)(b * H + h) * NN + i;
    float l = g_lpart[0][li] + g_lpart[1][li];
    float inv = (l > 0.f) ? (1.f / l) : 0.f;
    float4 o0 = *(const float4*)(g_opart[0] + flat);
    float4 o1 = *(const float4*)(g_opart[1] + flat);
    float4 w = {(o0.x + o1.x) * inv, (o0.y + o1.y) * inv,
                (o0.z + o1.z) * inv, (o0.w + o1.w) * inv};
    *(float4*)(out + flat) = w;
}

extern "C" void kernel_launch(void* const* d_in, const int* in_sizes, int n_in,
                              void* d_out, int out_size) {
    const float* xs   = (const float*)d_in[0];
    const float* adjs = (const float*)d_in[1];
    const float* W1   = (const float*)d_in[2];
    const float* a_l  = (const float*)d_in[3];
    const float* a_r  = (const float*)d_in[4];
    float* out = (float*)d_out;

    cudaFuncSetAttribute(k2_attn, cudaFuncAttributeMaxDynamicSharedMemorySize, SMEM_K2);

    k1_gemm<<<dim3(32, 4, 4), 256>>>(xs, W1, a_l, a_r);
    k1b_max<<<16, 256>>>();
    k2_attn<<<dim3(32, 2, 4), 256, SMEM_K2>>>(adjs);
    k3_combine<<<(BS * NN * HD / 4) / 256, 256>>>(out);
}

// round 7
// speedup vs baseline: 4.7361x; 1.3998x over previous
#include <cuda_runtime.h>
#include <cuda_fp16.h>
#include <cstdint>

#define BS   4
#define NN   2048
#define CIN  128
#define COUT 64
#define H    4
#define HD   256
#define TI   64
#define TJ   64
#define JH   1024
#define NJT  16
#define LOG2E 1.4426950408889634f

// device scratch (allocation-free)
__device__ __half g_hs_h[(size_t)BS * H * COUT * NN];  // [bh][d][n] fp16 (transposed)
__device__ float g_el[BS * H * NN];                    // pre-scaled by log2e
__device__ float g_er[BS * H * NN];                    // pre-scaled by log2e
__device__ float g_emax[BS * H];
__device__ float g_opart[2][(size_t)BS * NN * HD];
__device__ float g_lpart[2][BS * H * NN];

// K2 smem layout
#define PSTR 72                       // halfs per P/HS row
#define PBUF_BYTES  9216              // 64*72*2
#define HSBUF_BYTES 10368             // 72*72*2 (rows 64..71 = ones block)
#define OFF_HS_BYTES 18432            // after 2 P buffers
#define OFF_ER_F 9792                 // float idx: per buf {er[64],B[64],D[64]} x2
#define OFF_EL_F 10176                // per head {el[64],A[64],C[64]} x4
#define SMEM_K2 44032

__device__ __forceinline__ uint32_t smem_u32(const void* p) {
    uint32_t a;
    asm("{ .reg .u64 t; cvta.to.shared.u64 t, %1; cvt.u32.u64 %0, t; }" : "=r"(a) : "l"(p));
    return a;
}
__device__ __forceinline__ float ex2f(float x) {
    float r;
    asm("ex2.approx.f32 %0, %1;" : "=f"(r) : "f"(x));
    return r;
}
__device__ __forceinline__ void mma_f16(float* d, const uint32_t* a, const uint32_t* b) {
    asm volatile(
        "mma.sync.aligned.m16n8k16.row.col.f32.f16.f16.f32 "
        "{%0,%1,%2,%3}, {%4,%5,%6,%7}, {%8,%9}, {%0,%1,%2,%3};"
        : "+f"(d[0]), "+f"(d[1]), "+f"(d[2]), "+f"(d[3])
        : "r"(a[0]), "r"(a[1]), "r"(a[2]), "r"(a[3]), "r"(b[0]), "r"(b[1]));
}
__device__ __forceinline__ void ldsm_x4(uint32_t* r, uint32_t addr) {
    asm volatile("ldmatrix.sync.aligned.m8n8.x4.shared.b16 {%0,%1,%2,%3}, [%4];"
                 : "=r"(r[0]), "=r"(r[1]), "=r"(r[2]), "=r"(r[3]) : "r"(addr));
}
__device__ __forceinline__ void ldsm_x2(uint32_t* r, uint32_t addr) {
    asm volatile("ldmatrix.sync.aligned.m8n8.x2.shared.b16 {%0,%1}, [%2];"
                 : "=r"(r[0]), "=r"(r[1]) : "r"(addr));
}
__device__ __forceinline__ void cp16(uint32_t dst, const void* src) {
    asm volatile("cp.async.ca.shared.global [%0], [%1], 16;" :: "r"(dst), "l"(src));
}
#define CP_COMMIT asm volatile("cp.async.commit_group;" ::: "memory")
#define CP_WAIT0  asm volatile("cp.async.wait_group 0;" ::: "memory")
#define BARS(id, n) asm volatile("bar.sync %0, %1;" :: "r"(id), "r"(n) : "memory")
#define BARA(id, n) asm volatile("bar.arrive %0, %1;" :: "r"(id), "r"(n) : "memory")

// ---------------- K1: hs = xs @ W1 -> g_hs_h (transposed fp16), scaled el/er ----------------
__global__ __launch_bounds__(256) void k1_gemm(const float* __restrict__ xs,
                                               const float* __restrict__ W1,
                                               const float* __restrict__ a_l,
                                               const float* __restrict__ a_r) {
    const int bx = blockIdx.x, head = blockIdx.y, b = blockIdx.z;
    const int tid = threadIdx.x;
    const int ig = tid >> 4, cg = tid & 15;
    const int r0 = ig * 4, c0 = cg * 4;

    __shared__ float As[32][68];
    __shared__ float Bs[32][68];
    __shared__ float sred[16][64];

    float acc[4][4] = {};
    const float* xbase = xs + ((size_t)(b * NN + bx * 64)) * CIN;
    const float* wbase = W1 + head * COUT;

    for (int kc = 0; kc < CIN; kc += 32) {
        int lin = tid;
        #pragma unroll
        for (int t = 0; t < 2; t++, lin += 256) {
            int r = lin >> 3, k4 = lin & 7;
            float4 v = *(const float4*)(xbase + r * CIN + kc + k4 * 4);
            As[k4 * 4 + 0][r] = v.x; As[k4 * 4 + 1][r] = v.y;
            As[k4 * 4 + 2][r] = v.z; As[k4 * 4 + 3][r] = v.w;
        }
        lin = tid;
        #pragma unroll
        for (int t = 0; t < 2; t++, lin += 256) {
            int k = lin >> 4, c4 = lin & 15;
            float4 v = *(const float4*)(wbase + (size_t)(kc + k) * HD + c4 * 4);
            *(float4*)&Bs[k][c4 * 4] = v;
        }
        __syncthreads();
        #pragma unroll
        for (int k = 0; k < 32; k++) {
            float4 aq = *(const float4*)&As[k][r0];
            float4 bq = *(const float4*)&Bs[k][c0];
            float ar[4] = {aq.x, aq.y, aq.z, aq.w};
            float br[4] = {bq.x, bq.y, bq.z, bq.w};
            #pragma unroll
            for (int r = 0; r < 4; r++)
                #pragma unroll
                for (int c = 0; c < 4; c++) acc[r][c] += ar[r] * br[c];
        }
        __syncthreads();
    }

    const int bh = b * H + head;
    // transposed fp16 store: g_hs_h[bh][d][n]
    #pragma unroll
    for (int c = 0; c < 4; c++) {
        __half2 lo = __floats2half2_rn(acc[0][c], acc[1][c]);
        __half2 hi = __floats2half2_rn(acc[2][c], acc[3][c]);
        uint2 w = {*(uint32_t*)&lo, *(uint32_t*)&hi};
        *(uint2*)(g_hs_h + ((size_t)(bh * COUT + c0 + c)) * NN + bx * 64 + r0) = w;
    }
    float pl[4] = {}, pr[4] = {};
    #pragma unroll
    for (int r = 0; r < 4; r++)
        #pragma unroll
        for (int c = 0; c < 4; c++) {
            pl[r] += acc[r][c] * __ldg(a_l + c0 + c);
            pr[r] += acc[r][c] * __ldg(a_r + c0 + c);
        }
    #pragma unroll
    for (int r = 0; r < 4; r++) sred[cg][r0 + r] = pl[r];
    __syncthreads();
    if (tid < 64) {
        float s = 0.f;
        #pragma unroll
        for (int g = 0; g < 16; g++) s += sred[g][tid];
        g_el[(size_t)bh * NN + bx * 64 + tid] = s * LOG2E;
    }
    __syncthreads();
    #pragma unroll
    for (int r = 0; r < 4; r++) sred[cg][r0 + r] = pr[r];
    __syncthreads();
    if (tid < 64) {
        float s = 0.f;
        #pragma unroll
        for (int g = 0; g < 16; g++) s += sred[g][tid];
        g_er[(size_t)bh * NN + bx * 64 + tid] = s * LOG2E;
    }
}

// ---------------- K1b: emax (scaled domain) ----------------
__global__ void k1b_max() {
    const int bh = blockIdx.x;
    __shared__ float sm[256];
    float m = -1e30f;
    for (int i = threadIdx.x; i < NN; i += 256)
        m = fmaxf(m, g_er[(size_t)bh * NN + i]);
    sm[threadIdx.x] = m;
    __syncthreads();
    for (int s = 128; s > 0; s >>= 1) {
        if (threadIdx.x < s) sm[threadIdx.x] = fmaxf(sm[threadIdx.x], sm[threadIdx.x + s]);
        __syncthreads();
    }
    if (threadIdx.x == 0) g_emax[bh] = sm[0];
}

// ---------------- K2 builder iteration ----------------
__device__ __forceinline__ void builder_iter(
    float* sm, __half* smh, uint32_t smb, const float* __restrict__ adjs,
    int b, int i0, int half_, int bt, int c4, int rb,
    int h, int jt, float Eh,
    const float* rel, const float* rA, const float* rC,
    float4* cur, float4* nxt)
{
    const int g = h * NJT + jt, buf = g & 1;
    const int bh = b * H + h;
    const int jbase = half_ * JH + jt * TJ;
    // prefetch next adj tile into regs (adj is h-independent)
    {
        const int jn = half_ * JH + ((jt + 1) & 15) * TJ;
        const float* apn = adjs + ((size_t)(b * NN + i0 + rb)) * NN + jn + c4 * 4;
        #pragma unroll
        for (int v = 0; v < 8; v++) nxt[v] = *(const float4*)(apn + (size_t)(v * 8) * NN);
    }
    if (g >= 2) BARS(3 + buf, 256);
    // stage er / B / D factors (64 threads, 2 MUFU each)
    if (bt < 64) {
        float er = g_er[(size_t)bh * NN + jbase + bt];
        float u = er - Eh;
        sm[OFF_ER_F + buf * 192 + bt] = er;
        sm[OFF_ER_F + buf * 192 + 64 + bt] = ex2f(u);
        sm[OFF_ER_F + buf * 192 + 128 + bt] = ex2f(0.1f * u);
    }
    // cp.async HS fp16 tile [64 d][64 j]
    {
        uint32_t hB = smb + OFF_HS_BYTES + buf * HSBUF_BYTES;
        const __half* hsrc = g_hs_h + (size_t)bh * COUT * NN + jbase;
        #pragma unroll
        for (int v = 0; v < 4; v++) {
            int idx = bt + v * 128;
            int d = idx >> 3, j8 = idx & 7;
            cp16(hB + (uint32_t)(d * PSTR + j8 * 8) * 2, hsrc + (size_t)d * NN + j8 * 8);
        }
        CP_COMMIT;
    }
    BARS(5, 128);
    // build P (factorized exp, no MUFU): p = adj * (s>0 ? A*B : C*D)
    {
        float4 er4 = *(const float4*)(sm + OFF_ER_F + buf * 192 + c4 * 4);
        float4 B4  = *(const float4*)(sm + OFF_ER_F + buf * 192 + 64 + c4 * 4);
        float4 D4  = *(const float4*)(sm + OFF_ER_F + buf * 192 + 128 + c4 * 4);
        const float* erv = (const float*)&er4;
        const float* Bv  = (const float*)&B4;
        const float* Dv  = (const float*)&D4;
        __half* sPb = smh + (buf * PBUF_BYTES) / 2;
        #pragma unroll
        for (int v = 0; v < 8; v++) {
            int r = rb + v * 8;
            const float* av = (const float*)&cur[v];
            float p[4];
            #pragma unroll
            for (int e = 0; e < 4; e++) {
                float s = rel[v] + erv[e];
                float f1 = (s > 0.f) ? rA[v] : rC[v];
                float f2 = (s > 0.f) ? Bv[e] : Dv[e];
                p[e] = av[e] * f1 * f2;
            }
            __half2 p01 = __floats2half2_rn(p[0], p[1]);
            __half2 p23 = __floats2half2_rn(p[2], p[3]);
            uint2 w = {*(uint32_t*)&p01, *(uint32_t*)&p23};
            *(uint2*)(sPb + r * PSTR + c4 * 4) = w;
        }
    }
    CP_WAIT0;
    BARA(1 + buf, 256);
}

// ---------------- K2: warp-specialized fp16 mma flash loop ----------------
__global__ __launch_bounds__(256, 2) void k2_attn(const float* __restrict__ adjs) {
    extern __shared__ float sm[];
    __half* smh = (__half*)sm;
    const uint32_t smb = smem_u32(sm);
    const int tid = threadIdx.x, wid = tid >> 5, lane = tid & 31;
    const int i0 = blockIdx.x * TI, half_ = blockIdx.y, b = blockIdx.z;

    // init ones rows (64..71) of both HS buffers
    for (int idx = tid; idx < 2 * 8 * PSTR; idx += 256) {
        int buf = idx / (8 * PSTR);
        int rem = idx % (8 * PSTR);
        int r8 = rem / PSTR, c = rem % PSTR;
        smh[(OFF_HS_BYTES + buf * HSBUF_BYTES) / 2 + (64 + r8) * PSTR + c] =
            (r8 == 0 && c < 64) ? __float2half(1.f) : __float2half(0.f);
    }
    // prologue: el / A / C per head
    if (tid < 256) {
        int h = tid >> 6, r = tid & 63;
        int bh = b * H + h;
        float e = g_el[(size_t)bh * NN + i0 + r];
        float E = g_emax[bh];
        float t = e + E;
        float m = fmaxf(t, 0.1f * t);
        sm[OFF_EL_F + h * 192 + r] = e;
        sm[OFF_EL_F + h * 192 + 64 + r] = ex2f(t - m);
        sm[OFF_EL_F + h * 192 + 128 + r] = ex2f(0.1f * t - m);
    }
    __syncthreads();

    if (wid >= 4) {
        // ---------------- builders ----------------
        const int bt = tid & 127;
        const int c4 = bt & 15, rb = bt >> 4;
        float4 ajA[8], ajB[8];
        {
            const float* ap0 = adjs + ((size_t)(b * NN + i0 + rb)) * NN + half_ * JH + c4 * 4;
            #pragma unroll
            for (int v = 0; v < 8; v++) ajA[v] = *(const float4*)(ap0 + (size_t)(v * 8) * NN);
        }
        for (int h = 0; h < H; h++) {
            const float Eh = g_emax[b * H + h];
            float rel[8], rA[8], rC[8];
            #pragma unroll
            for (int v = 0; v < 8; v++) {
                int r = rb + v * 8;
                rel[v] = sm[OFF_EL_F + h * 192 + r];
                rA[v]  = sm[OFF_EL_F + h * 192 + 64 + r];
                rC[v]  = sm[OFF_EL_F + h * 192 + 128 + r];
            }
            #pragma unroll 1
            for (int jp = 0; jp < 8; jp++) {
                builder_iter(sm, smh, smb, adjs, b, i0, half_, bt, c4, rb,
                             h, 2 * jp, Eh, rel, rA, rC, ajA, ajB);
                builder_iter(sm, smh, smb, adjs, b, i0, half_, bt, c4, rb,
                             h, 2 * jp + 1, Eh, rel, rA, rC, ajB, ajA);
            }
        }
    } else {
        // ---------------- consumers ----------------
        const int gid = lane >> 2, tg = lane & 3;
        const uint32_t aRow = (uint32_t)(wid * 16 + (lane & 7) + ((lane >> 3) & 1) * 8);
        const uint32_t aOff = (aRow * PSTR + (lane >> 4) * 8) * 2;
        const uint32_t bRowL = (uint32_t)((lane & 7) + (lane >> 4) * 8);
        const uint32_t bOff = (bRowL * PSTR + ((lane >> 3) & 1) * 8) * 2;
        const int ol = lane & 15;
        const uint32_t oOff = (uint32_t)(((64 + (ol & 7)) * PSTR + ((ol >> 3) & 1) * 8) * 2);
        for (int h = 0; h < H; h++) {
            const int bh = b * H + h;
            float acc[9][4];
            #pragma unroll
            for (int nc = 0; nc < 9; nc++)
                #pragma unroll
                for (int e = 0; e < 4; e++) acc[nc][e] = 0.f;
            for (int jt = 0; jt < NJT; jt++) {
                const int g = h * NJT + jt, buf = g & 1;
                BARS(1 + buf, 256);
                uint32_t pA = smb + buf * PBUF_BYTES + aOff;
                uint32_t hB = smb + OFF_HS_BYTES + buf * HSBUF_BYTES;
                #pragma unroll
                for (int ks = 0; ks < 4; ks++) {
                    uint32_t a[4];
                    ldsm_x4(a, pA); pA += 32;
                    #pragma unroll
                    for (int p2 = 0; p2 < 4; p2++) {
                        uint32_t bb[4];
                        ldsm_x4(bb, hB + bOff + (uint32_t)p2 * (16 * PSTR * 2) + ks * 32);
                        mma_f16(acc[2 * p2], a, bb);
                        mma_f16(acc[2 * p2 + 1], a, bb + 2);
                    }
                    uint32_t oo[2];
                    ldsm_x2(oo, hB + oOff + ks * 32);
                    mma_f16(acc[8], a, oo);
                }
                BARA(3 + buf, 256);
            }
            // epilogue: unnormalized O + l (ones column 64 -> acc[8][0]/acc[8][2])
            const int r0 = i0 + wid * 16 + gid;
            float* ob = g_opart[half_] + ((size_t)b * NN) * HD;
            #pragma unroll
            for (int nc = 0; nc < 8; nc++) {
                int col = h * 64 + nc * 8 + 2 * tg;
                float2 v0 = {acc[nc][0], acc[nc][1]};
                float2 v1 = {acc[nc][2], acc[nc][3]};
                *(float2*)(ob + (size_t)r0 * HD + col) = v0;
                *(float2*)(ob + (size_t)(r0 + 8) * HD + col) = v1;
            }
            if (tg == 0) {
                g_lpart[half_][(size_t)bh * NN + r0] = acc[8][0];
                g_lpart[half_][(size_t)bh * NN + r0 + 8] = acc[8][2];
            }
        }
    }
}

// ---------------- K3: combine halves + normalize ----------------
__global__ __launch_bounds__(256) void k3_combine(float* __restrict__ out) {
    int idx = blockIdx.x * 256 + threadIdx.x;
    size_t flat = (size_t)idx * 4;
    int b   = (int)(flat / ((size_t)NN * HD));
    int rem = (int)(flat % ((size_t)NN * HD));
    int i = rem / HD;
    int h = (rem % HD) >> 6;
    size_t li = (size_t)(b * H + h) * NN + i;
    float l = g_lpart[0][li] + g_lpart[1][li];
    float inv = (l > 0.f) ? (1.f / l) : 0.f;
    float4 o0 = *(const float4*)(g_opart[0] + flat);
    float4 o1 = *(const float4*)(g_opart[1] + flat);
    float4 w = {(o0.x + o1.x) * inv, (o0.y + o1.y) * inv,
                (o0.z + o1.z) * inv, (o0.w + o1.w) * inv};
    *(float4*)(out + flat) = w;
}

extern "C" void kernel_launch(void* const* d_in, const int* in_sizes, int n_in,
                              void* d_out, int out_size) {
    const float* xs   = (const float*)d_in[0];
    const float* adjs = (const float*)d_in[1];
    const float* W1   = (const float*)d_in[2];
    const float* a_l  = (const float*)d_in[3];
    const float* a_r  = (const float*)d_in[4];
    float* out = (float*)d_out;

    cudaFuncSetAttribute(k2_attn, cudaFuncAttributeMaxDynamicSharedMemorySize, SMEM_K2);

    k1_gemm<<<dim3(32, 4, 4), 256>>>(xs, W1, a_l, a_r);
    k1b_max<<<16, 256>>>();
    k2_attn<<<dim3(32, 2, 4), 256, SMEM_K2>>>(adjs);
    k3_combine<<<(BS * NN * HD / 4) / 256, 256>>>(out);
}